// round 15
// baseline (speedup 1.0000x reference)
#include <cuda_runtime.h>
#include <cuda_bf16.h>
#include <cstdint>

#define B_ 8
#define T_ 128
#define S_ 512
#define E_ 512
#define D_ 512

// ---------------- scratch (no allocs allowed) ----------------
__device__ __align__(256) float g_hp[B_*T_*D_];
__device__ __align__(256) float g_ep[B_*S_*D_];
__device__ __align__(256) float g_en[B_*T_*S_];
__device__ __align__(256) float g_p0[B_*T_*E_];   // split-K partials
__device__ __align__(256) float g_p1[B_*T_*E_];
__device__ __align__(256) float g_p2[B_*T_*E_];
__device__ __align__(256) float g_p3[B_*T_*E_];

__device__ __align__(256) __nv_bfloat16 g_hid_h[B_*T_*D_],  g_hid_l[B_*T_*D_];
__device__ __align__(256) __nv_bfloat16 g_enc_h[B_*S_*E_],  g_enc_l[B_*S_*E_];
__device__ __align__(256) __nv_bfloat16 g_encT_h[B_*E_*S_], g_encT_l[B_*E_*S_];
__device__ __align__(256) __nv_bfloat16 g_Wa_h[D_*(E_+D_)], g_Wa_l[D_*(E_+D_)];
__device__ __align__(256) __nv_bfloat16 g_Wo_h[D_*(E_+D_)], g_Wo_l[D_*(E_+D_)];
__device__ __align__(256) __nv_bfloat16 g_attn_h[B_*T_*S_], g_attn_l[B_*T_*S_];
__device__ __align__(256) __nv_bfloat16 g_wc_h[B_*T_*E_],   g_wc_l[B_*T_*E_];

__device__ __forceinline__ float tanh_fast(float x){
    float r; asm("tanh.approx.f32 %0, %1;" : "=f"(r) : "f"(x)); return r;
}
__device__ __forceinline__ uint32_t smem_u32(const void* p){
    uint32_t a;
    asm("{ .reg .u64 t; cvta.to.shared.u64 t, %1; cvt.u32.u64 %0, t; }" : "=r"(a) : "l"(p));
    return a;
}
__device__ __forceinline__ void cp16(uint32_t dst, const void* src){
    asm volatile("cp.async.cg.shared.global [%0], [%1], 16;" :: "r"(dst), "l"(src));
}
#define CP_COMMIT() asm volatile("cp.async.commit_group;" ::: "memory")
#define CP_WAIT(n)  asm volatile("cp.async.wait_group %0;" :: "n"(n) : "memory")

#define LDSM4(r, addr) \
    asm volatile("ldmatrix.sync.aligned.m8n8.x4.shared.b16 {%0,%1,%2,%3}, [%4];" \
        : "=r"((r)[0]), "=r"((r)[1]), "=r"((r)[2]), "=r"((r)[3]) : "r"(addr))

#define MMA16816(c, a, b0, b1) \
    asm volatile("mma.sync.aligned.m16n8k16.row.col.f32.bf16.bf16.f32 " \
        "{%0,%1,%2,%3}, {%4,%5,%6,%7}, {%8,%9}, {%0,%1,%2,%3};" \
        : "+f"((c)[0]), "+f"((c)[1]), "+f"((c)[2]), "+f"((c)[3]) \
        : "r"((a)[0]), "r"((a)[1]), "r"((a)[2]), "r"((a)[3]), "r"(b0), "r"(b1))

// ---------------------------------------------------------------------------
// Fused prep: splits for hidden/W_attn/W_out + enc split/transpose-split.
// ---------------------------------------------------------------------------
__global__ void prep_all_kernel(const float* __restrict__ x0, __nv_bfloat16* h0, __nv_bfloat16* l0, int b0,
                                const float* __restrict__ x1, __nv_bfloat16* h1, __nv_bfloat16* l1, int b1,
                                const float* __restrict__ x2, __nv_bfloat16* h2, __nv_bfloat16* l2, int b2,
                                const float* __restrict__ enc,
                                __nv_bfloat16* __restrict__ sh, __nv_bfloat16* __restrict__ sl,
                                __nv_bfloat16* __restrict__ th, __nv_bfloat16* __restrict__ tl)
{
    __shared__ float tile[32][33];
    int blk = blockIdx.x;
    int nsplit = b0 + b1 + b2;
    int tid = threadIdx.x;
    if (blk < nsplit){
        const float* x; __nv_bfloat16 *hi, *lo;
        if (blk < b0){ x = x0; hi = h0; lo = l0; }
        else if (blk < b0 + b1){ blk -= b0; x = x1; hi = h1; lo = l1; }
        else { blk -= b0 + b1; x = x2; hi = h2; lo = l2; }
        int i = (blk * 256 + tid) * 4;
        float4 v = *(const float4*)(x + i);
        float vv[4] = {v.x, v.y, v.z, v.w};
        __nv_bfloat16 h[4], l[4];
        #pragma unroll
        for (int j = 0; j < 4; j++){
            h[j] = __float2bfloat16_rn(vv[j]);
            l[j] = __float2bfloat16_rn(vv[j] - __bfloat162float(h[j]));
        }
        *(ushort4*)(hi + i) = *(ushort4*)h;
        *(ushort4*)(lo + i) = *(ushort4*)l;
        return;
    }
    int t = blk - nsplit;
    int b = t >> 8;
    int rem = t & 255;
    int s0 = (rem & 15) * 32, e0 = (rem >> 4) * 32;
    int tx = tid & 31, ty = tid >> 5;
    const float* src = enc + ((size_t)b * S_ + s0) * E_ + e0;
    for (int i = ty; i < 32; i += 8){
        float v = src[(size_t)i * E_ + tx];
        tile[i][tx] = v;
        __nv_bfloat16 h = __float2bfloat16_rn(v);
        __nv_bfloat16 l = __float2bfloat16_rn(v - __bfloat162float(h));
        size_t o = ((size_t)b * S_ + s0 + i) * E_ + e0 + tx;
        sh[o] = h; sl[o] = l;
    }
    __syncthreads();
    for (int i = ty; i < 32; i += 8){
        float v = tile[tx][i];
        __nv_bfloat16 h = __float2bfloat16_rn(v);
        __nv_bfloat16 l = __float2bfloat16_rn(v - __bfloat162float(h));
        size_t o = ((size_t)b * E_ + e0 + i) * S_ + s0 + tx;
        th[o] = h; tl[o] = l;
    }
}

// ---------------------------------------------------------------------------
// Common constants
// ---------------------------------------------------------------------------
#define RS      80

// ---- 64x64 core (for split-K kernels): 128 thr, 4 warps 2m x 2n ----
#define OFF_AL  (64*RS)
#define OFF_BH  (128*RS)
#define OFF_BL  (192*RS)
#define STG64   (256*RS)        // 20480 B
#define GS64    (2*STG64)       // 40960 B

__device__ __forceinline__ void fill64(uint32_t st,
    const __nv_bfloat16* ah, const __nv_bfloat16* al, int lda,
    const __nv_bfloat16* bh, const __nv_bfloat16* bl, int ldb, int tid)
{
    #pragma unroll
    for (int j = 0; j < 8; j++){
        int i = tid + j * 128;
        int r = i >> 2, s = i & 3, rr = r & 63;
        const __nv_bfloat16* src;
        int reg = r >> 6;
        if (reg == 0)      src = ah + (size_t)rr * lda + s * 8;
        else if (reg == 1) src = al + (size_t)rr * lda + s * 8;
        else if (reg == 2) src = bh + (size_t)rr * ldb + s * 8;
        else               src = bl + (size_t)rr * ldb + s * 8;
        cp16(st + (uint32_t)(r * RS + s * 16), src);
    }
    CP_COMMIT();
}

__device__ __forceinline__ void gemm64_core(uint32_t sb, int tid, int chunks,
    const __nv_bfloat16* ah, const __nv_bfloat16* al, int lda,
    const __nv_bfloat16* bh, const __nv_bfloat16* bl, int ldb,
    float (&acc)[2][4][4])
{
    int wid = tid >> 5, lane = tid & 31;
    int wm = (wid & 1) * 32, wn = (wid >> 1) * 32;
    int quad = lane >> 3, lr = lane & 7;
    uint32_t a_off[2], b_off[2];
    #pragma unroll
    for (int mt = 0; mt < 2; mt++)
        a_off[mt] = (uint32_t)((wm + mt*16 + (quad & 1)*8 + lr) * RS + (quad >> 1)*16);
    #pragma unroll
    for (int p = 0; p < 2; p++)
        b_off[p]  = (uint32_t)((wn + p*16 + (quad >> 1)*8 + lr) * RS + (quad & 1)*16);

    fill64(sb, ah, al, lda, bh, bl, ldb, tid);

    for (int c = 0; c < chunks; c++){
        if (c + 1 < chunks){
            int ko = (c + 1) * 32;
            fill64(sb + ((c + 1) & 1)*STG64, ah + ko, al + ko, lda, bh + ko, bl + ko, ldb, tid);
            CP_WAIT(1);
        } else {
            CP_WAIT(0);
        }
        __syncthreads();
        uint32_t st = sb + (c & 1)*STG64;
        #pragma unroll
        for (int ks = 0; ks < 2; ks++){
            uint32_t koff = ks * 32;
            uint32_t ah_[2][4], al_[2][4], bh_[2][4], bl_[2][4];
            #pragma unroll
            for (int mt = 0; mt < 2; mt++){
                LDSM4(ah_[mt], st + a_off[mt] + koff);
                LDSM4(al_[mt], st + OFF_AL + a_off[mt] + koff);
            }
            #pragma unroll
            for (int p = 0; p < 2; p++){
                LDSM4(bh_[p], st + OFF_BH + b_off[p] + koff);
                LDSM4(bl_[p], st + OFF_BL + b_off[p] + koff);
            }
            #pragma unroll
            for (int mt = 0; mt < 2; mt++)
                #pragma unroll
                for (int nt = 0; nt < 4; nt++){
                    int p = nt >> 1, q = (nt & 1) * 2;
                    MMA16816(acc[mt][nt], ah_[mt], bh_[p][q], bh_[p][q+1]);
                    MMA16816(acc[mt][nt], ah_[mt], bl_[p][q], bl_[p][q+1]);
                    MMA16816(acc[mt][nt], al_[mt], bh_[p][q], bh_[p][q+1]);
                }
        }
        __syncthreads();
    }
}

// ---- 64x128 dual kernel (hp + ep): 128 thr, 4 warps 2m x 2n, warp 32x64 ----
#define N_OFF_AL  (64*RS)
#define N_OFF_BH  (128*RS)
#define N_OFF_BL  (256*RS)
#define STG128N   (384*RS)        // 30720 B
#define GS128N    (2*STG128N)     // 61440 B -> 3 CTAs/SM

__device__ __forceinline__ void fill128n(uint32_t st,
    const __nv_bfloat16* ah, const __nv_bfloat16* al, int lda,
    const __nv_bfloat16* bh, const __nv_bfloat16* bl, int ldb, int tid)
{
    #pragma unroll
    for (int j = 0; j < 12; j++){
        int i = tid + j * 128;
        int r = i >> 2, s = i & 3;
        const __nv_bfloat16* src;
        if (r < 64)       src = ah + (size_t)r * lda + s * 8;
        else if (r < 128) src = al + (size_t)(r - 64) * lda + s * 8;
        else if (r < 256) src = bh + (size_t)(r - 128) * ldb + s * 8;
        else              src = bl + (size_t)(r - 256) * ldb + s * 8;
        cp16(st + (uint32_t)(r * RS + s * 16), src);
    }
    CP_COMMIT();
}

__global__ void __launch_bounds__(128)
gemm128n_dual_kernel(const __nv_bfloat16* __restrict__ a0h, const __nv_bfloat16* __restrict__ a0l, int lda0,
                     const __nv_bfloat16* __restrict__ b0h, const __nv_bfloat16* __restrict__ b0l, int ldb0,
                     float* __restrict__ C0, int ldc0, const float* __restrict__ bias0, int mt0, int nblk0,
                     const __nv_bfloat16* __restrict__ a1h, const __nv_bfloat16* __restrict__ a1l, int lda1,
                     const __nv_bfloat16* __restrict__ b1h, const __nv_bfloat16* __restrict__ b1l, int ldb1,
                     float* __restrict__ C1, int ldc1, int mt1,
                     int chunks)
{
    extern __shared__ __align__(16) char smem[];
    uint32_t sb = smem_u32(smem);
    int tid = threadIdx.x, bx = blockIdx.x;

    const __nv_bfloat16 *ah, *al, *bh, *bl; const float* bias;
    float* C; int lda, ldb, ldc, m0, n0;
    if (bx < nblk0){
        m0 = (bx % mt0) * 64; n0 = (bx / mt0) * 128;
        ah = a0h; al = a0l; lda = lda0; bh = b0h; bl = b0l; ldb = ldb0;
        C = C0; ldc = ldc0; bias = bias0;
    } else {
        int b2 = bx - nblk0;
        m0 = (b2 % mt1) * 64; n0 = (b2 / mt1) * 128;
        ah = a1h; al = a1l; lda = lda1; bh = b1h; bl = b1l; ldb = ldb1;
        C = C1; ldc = ldc1; bias = nullptr;
    }
    ah += (size_t)m0 * lda; al += (size_t)m0 * lda;
    bh += (size_t)n0 * ldb; bl += (size_t)n0 * ldb;

    int wid = tid >> 5, lane = tid & 31;
    int wm = (wid & 1) * 32, wn = (wid >> 1) * 64;
    int quad = lane >> 3, lr = lane & 7;
    uint32_t a_off[2], b_off[4];
    #pragma unroll
    for (int mt = 0; mt < 2; mt++)
        a_off[mt] = (uint32_t)((wm + mt*16 + (quad & 1)*8 + lr) * RS + (quad >> 1)*16);
    #pragma unroll
    for (int p = 0; p < 4; p++)
        b_off[p]  = (uint32_t)((wn + p*16 + (quad >> 1)*8 + lr) * RS + (quad & 1)*16);

    float acc[2][8][4] = {};

    fill128n(sb, ah, al, lda, bh, bl, ldb, tid);

    for (int c = 0; c < chunks; c++){
        if (c + 1 < chunks){
            int ko = (c + 1) * 32;
            fill128n(sb + ((c + 1) & 1)*STG128N, ah + ko, al + ko, lda, bh + ko, bl + ko, ldb, tid);
            CP_WAIT(1);
        } else {
            CP_WAIT(0);
        }
        __syncthreads();
        uint32_t st = sb + (c & 1)*STG128N;
        #pragma unroll
        for (int ks = 0; ks < 2; ks++){
            uint32_t koff = ks * 32;
            uint32_t ah_[2][4], al_[2][4], bh_[4][4], bl_[4][4];
            #pragma unroll
            for (int mt = 0; mt < 2; mt++){
                LDSM4(ah_[mt], st + a_off[mt] + koff);
                LDSM4(al_[mt], st + N_OFF_AL + a_off[mt] + koff);
            }
            #pragma unroll
            for (int p = 0; p < 4; p++){
                LDSM4(bh_[p], st + N_OFF_BH + b_off[p] + koff);
                LDSM4(bl_[p], st + N_OFF_BL + b_off[p] + koff);
            }
            #pragma unroll
            for (int mt = 0; mt < 2; mt++)
                #pragma unroll
                for (int nt = 0; nt < 8; nt++){
                    int p = nt >> 1, q = (nt & 1) * 2;
                    MMA16816(acc[mt][nt], ah_[mt], bh_[p][q], bh_[p][q+1]);
                    MMA16816(acc[mt][nt], ah_[mt], bl_[p][q], bl_[p][q+1]);
                    MMA16816(acc[mt][nt], al_[mt], bh_[p][q], bh_[p][q+1]);
                }
        }
        __syncthreads();
    }

    #pragma unroll
    for (int mt = 0; mt < 2; mt++){
        int r = m0 + wm + mt*16 + (lane >> 2);
        #pragma unroll
        for (int nt = 0; nt < 8; nt++){
            int col = n0 + wn + nt*8 + (lane & 3)*2;
            float c0 = acc[mt][nt][0], c1 = acc[mt][nt][1];
            float c2 = acc[mt][nt][2], c3 = acc[mt][nt][3];
            if (bias){
                float bb0 = bias[col], bb1 = bias[col+1];
                c0 += bb0; c1 += bb1; c2 += bb0; c3 += bb1;
            }
            *(float2*)(C + (size_t)r * ldc + col)       = make_float2(c0, c1);
            *(float2*)(C + (size_t)(r + 8) * ldc + col) = make_float2(c2, c3);
        }
    }
}

// ---- split-K (x4) batched GEMM into partial buffers P0..P3 ----
__global__ void __launch_bounds__(128)
gemm64_ks4_kernel(const __nv_bfloat16* __restrict__ A0h, const __nv_bfloat16* __restrict__ A0l,
                  const __nv_bfloat16* __restrict__ A1h, const __nv_bfloat16* __restrict__ A1l,
                  int ksplitA, int kstep, int lda, long long sA,
                  const __nv_bfloat16* __restrict__ Bh, const __nv_bfloat16* __restrict__ Bl,
                  int ldb, long long sB,
                  float* __restrict__ P0, float* __restrict__ P1,
                  float* __restrict__ P2, float* __restrict__ P3,
                  int ldp, long long sP,
                  int chunks, int mtiles)
{
    extern __shared__ __align__(16) char smem[];
    uint32_t sb = smem_u32(smem);
    int tid = threadIdx.x;
    int ks = blockIdx.x / mtiles;
    int m0 = (blockIdx.x % mtiles) * 64, n0 = blockIdx.y * 64, z = blockIdx.z;

    int second = (ks >= ksplitA);
    int kse = second ? (ks - ksplitA) : ks;
    const __nv_bfloat16* ah = (second ? A1h : A0h) + (size_t)z*sA + (size_t)m0*lda + (size_t)kse*kstep;
    const __nv_bfloat16* al = (second ? A1l : A0l) + (size_t)z*sA + (size_t)m0*lda + (size_t)kse*kstep;
    const __nv_bfloat16* bh = Bh + (size_t)z*sB + (size_t)n0*ldb + (size_t)ks*kstep;
    const __nv_bfloat16* bl = Bl + (size_t)z*sB + (size_t)n0*ldb + (size_t)ks*kstep;

    float acc[2][4][4] = {};
    gemm64_core(sb, tid, chunks, ah, al, lda, bh, bl, ldb, acc);

    float* P = (ks == 0 ? P0 : ks == 1 ? P1 : ks == 2 ? P2 : P3) + (size_t)z * sP;
    int wid = tid >> 5, lane = tid & 31;
    int wm = (wid & 1) * 32, wn = (wid >> 1) * 32;
    #pragma unroll
    for (int mt = 0; mt < 2; mt++){
        int r = m0 + wm + mt*16 + (lane >> 2);
        #pragma unroll
        for (int nt = 0; nt < 4; nt++){
            int col = n0 + wn + nt*8 + (lane & 3)*2;
            *(float2*)(P + (size_t)r * ldp + col)       = make_float2(acc[mt][nt][0], acc[mt][nt][1]);
            *(float2*)(P + (size_t)(r + 8) * ldp + col) = make_float2(acc[mt][nt][2], acc[mt][nt][3]);
        }
    }
}

// ---- combine 4 partials ----
__global__ void combine_wc_kernel(const float* __restrict__ p0, const float* __restrict__ p1,
                                  const float* __restrict__ p2, const float* __restrict__ p3,
                                  float* __restrict__ wc,
                                  __nv_bfloat16* __restrict__ ch, __nv_bfloat16* __restrict__ cl)
{
    int i = (blockIdx.x * 256 + threadIdx.x) * 4;
    float4 a = *(const float4*)(p0 + i);
    float4 b = *(const float4*)(p1 + i);
    float4 c = *(const float4*)(p2 + i);
    float4 d = *(const float4*)(p3 + i);
    float v[4] = {((a.x + b.x) + c.x) + d.x, ((a.y + b.y) + c.y) + d.y,
                  ((a.z + b.z) + c.z) + d.z, ((a.w + b.w) + c.w) + d.w};
    *(float4*)(wc + i) = make_float4(v[0], v[1], v[2], v[3]);
    __nv_bfloat16 h[4], l[4];
    #pragma unroll
    for (int j = 0; j < 4; j++){
        h[j] = __float2bfloat16_rn(v[j]);
        l[j] = __float2bfloat16_rn(v[j] - __bfloat162float(h[j]));
    }
    *(ushort4*)(ch + i) = *(ushort4*)h;
    *(ushort4*)(cl + i) = *(ushort4*)l;
}

__global__ void combine_ht_kernel(const float* __restrict__ p0, const float* __restrict__ p1,
                                  const float* __restrict__ p2, const float* __restrict__ p3,
                                  float* __restrict__ ht)
{
    int i = (blockIdx.x * 256 + threadIdx.x) * 4;
    float4 a = *(const float4*)(p0 + i);
    float4 b = *(const float4*)(p1 + i);
    float4 c = *(const float4*)(p2 + i);
    float4 d = *(const float4*)(p3 + i);
    *(float4*)(ht + i) = make_float4(tanh_fast(((a.x + b.x) + c.x) + d.x),
                                     tanh_fast(((a.y + b.y) + c.y) + d.y),
                                     tanh_fast(((a.z + b.z) + c.z) + d.z),
                                     tanh_fast(((a.w + b.w) + c.w) + d.w));
}

// ---------------------------------------------------------------------------
// energies: 16t x 64s, BK=32, register prefetch (proven config, 73.4us)
// ---------------------------------------------------------------------------
__global__ void energies_kernel(const float* __restrict__ hp,
                                const float* __restrict__ ep,
                                const float* __restrict__ wv,
                                const float* __restrict__ bv,
                                const float* __restrict__ mask,
                                float* __restrict__ en)
{
    __shared__ __align__(16) float hps[32][17];
    __shared__ __align__(16) float eps[32][65];
    __shared__ float wvs[32];
    int b = blockIdx.z, t0 = blockIdx.y * 16, s0 = blockIdx.x * 64;
    int tid = threadIdx.x;
    int sx = tid & 31, ty = tid >> 5;
    const float* hpb = hp + (size_t)(b*T_ + t0) * D_;
    const float* epb = ep + (size_t)(b*S_ + s0) * D_;
    float a00=0.f, a01=0.f, a10=0.f, a11=0.f;
    int ht = tid >> 4, hk = (tid & 15) << 1;
    int es = tid >> 2, ek = (tid & 3) << 3;

    float2 hv = *(const float2*)(hpb + (size_t)ht*D_ + hk);
    float4 e0v = *(const float4*)(epb + (size_t)es*D_ + ek);
    float4 e1v = *(const float4*)(epb + (size_t)es*D_ + ek + 4);
    float wvv = (tid < 32) ? wv[tid] : 0.f;

    for (int k0 = 0; k0 < D_; k0 += 32) {
        hps[hk][ht] = hv.x; hps[hk+1][ht] = hv.y;
        eps[ek+0][es]=e0v.x; eps[ek+1][es]=e0v.y; eps[ek+2][es]=e0v.z; eps[ek+3][es]=e0v.w;
        eps[ek+4][es]=e1v.x; eps[ek+5][es]=e1v.y; eps[ek+6][es]=e1v.z; eps[ek+7][es]=e1v.w;
        if (tid < 32) wvs[tid] = wvv;
        __syncthreads();
        if (k0 + 32 < D_){
            int kn = k0 + 32;
            hv  = *(const float2*)(hpb + (size_t)ht*D_ + kn + hk);
            e0v = *(const float4*)(epb + (size_t)es*D_ + kn + ek);
            e1v = *(const float4*)(epb + (size_t)es*D_ + kn + ek + 4);
            if (tid < 32) wvv = wv[kn + tid];
        }
        #pragma unroll
        for (int k = 0; k < 32; k++) {
            float w  = wvs[k];
            float h0 = hps[k][ty], h1 = hps[k][ty+8];
            float e0 = eps[k][sx], e1 = eps[k][sx+32];
            a00 = fmaf(w, tanh_fast(h0+e0), a00);
            a01 = fmaf(w, tanh_fast(h0+e1), a01);
            a10 = fmaf(w, tanh_fast(h1+e0), a10);
            a11 = fmaf(w, tanh_fast(h1+e1), a11);
        }
        __syncthreads();
    }
    float bb  = bv[0];
    float mv0 = mask[(size_t)b*S_ + s0 + sx];
    float mv1 = mask[(size_t)b*S_ + s0 + sx + 32];
    size_t r0 = (size_t)(b*T_ + t0 + ty)     * S_ + s0;
    size_t r1 = (size_t)(b*T_ + t0 + ty + 8) * S_ + s0;
    en[r0 + sx]      = (a00 + bb) * mv0;
    en[r0 + sx + 32] = (a01 + bb) * mv1;
    en[r1 + sx]      = (a10 + bb) * mv0;
    en[r1 + sx + 32] = (a11 + bb) * mv1;
}

// ---------------------------------------------------------------------------
// masked softmax + bf16 split of attn weights
// ---------------------------------------------------------------------------
__global__ void softmax_kernel(const float* __restrict__ en,
                               const float* __restrict__ mask,
                               float* __restrict__ attn,
                               __nv_bfloat16* __restrict__ ah,
                               __nv_bfloat16* __restrict__ al)
{
    int r = blockIdx.x;
    int b = r >> 7;
    const float* e = en + (size_t)r * S_;
    const float* m = mask + (size_t)b * S_;
    int tid = threadIdx.x;
    float m0v = m[tid], m1v = m[tid + 256];
    float x0 = e[tid] * m0v, x1 = e[tid + 256] * m1v;
    float mx = fmaxf(x0, x1);
    #pragma unroll
    for (int o = 16; o; o >>= 1) mx = fmaxf(mx, __shfl_xor_sync(0xffffffffu, mx, o));
    __shared__ float red[8];
    int w = tid >> 5, l = tid & 31;
    if (l == 0) red[w] = mx;
    __syncthreads();
    mx = red[0];
    #pragma unroll
    for (int i = 1; i < 8; i++) mx = fmaxf(mx, red[i]);
    float e0 = __expf(x0 - mx) * m0v;
    float e1 = __expf(x1 - mx) * m1v;
    float s = e0 + e1;
    #pragma unroll
    for (int o = 16; o; o >>= 1) s += __shfl_xor_sync(0xffffffffu, s, o);
    __syncthreads();
    if (l == 0) red[w] = s;
    __syncthreads();
    float tot = 0.f;
    #pragma unroll
    for (int i = 0; i < 8; i++) tot += red[i];
    float inv = 1.0f / (tot + 1e-6f);
    float a0 = e0 * inv, a1 = e1 * inv;
    size_t base = (size_t)r * S_;
    attn[base + tid]       = a0;
    attn[base + tid + 256] = a1;
    __nv_bfloat16 h0 = __float2bfloat16_rn(a0);
    __nv_bfloat16 h1 = __float2bfloat16_rn(a1);
    ah[base + tid]       = h0;
    ah[base + tid + 256] = h1;
    al[base + tid]       = __float2bfloat16_rn(a0 - __bfloat162float(h0));
    al[base + tid + 256] = __float2bfloat16_rn(a1 - __bfloat162float(h1));
}

// ---------------------------------------------------------------------------
extern "C" void kernel_launch(void* const* d_in, const int* in_sizes, int n_in,
                              void* d_out, int out_size)
{
    const float* hidden = (const float*)d_in[0];
    const float* enc    = (const float*)d_in[1];
    const float* mask   = (const float*)d_in[2];
    const float* W_attn = (const float*)d_in[3];
    const float* b_attn = (const float*)d_in[4];
    const float* W_v    = (const float*)d_in[5];
    const float* b_v    = (const float*)d_in[6];
    const float* W_out  = (const float*)d_in[7];

    float* out     = (float*)d_out;
    float* h_tilde = out;
    float* wc      = out + (size_t)B_*T_*D_;
    float* attn    = wc  + (size_t)B_*T_*E_;

    float *hp, *ep, *en, *p0, *p1, *p2, *p3;
    cudaGetSymbolAddress((void**)&hp, g_hp);
    cudaGetSymbolAddress((void**)&ep, g_ep);
    cudaGetSymbolAddress((void**)&en, g_en);
    cudaGetSymbolAddress((void**)&p0, g_p0);
    cudaGetSymbolAddress((void**)&p1, g_p1);
    cudaGetSymbolAddress((void**)&p2, g_p2);
    cudaGetSymbolAddress((void**)&p3, g_p3);
    __nv_bfloat16 *hid_h,*hid_l,*enc_h,*enc_l,*encT_h,*encT_l,*Wa_h,*Wa_l,*Wo_h,*Wo_l,*at_h,*at_l,*wc_h,*wc_l;
    cudaGetSymbolAddress((void**)&hid_h, g_hid_h);  cudaGetSymbolAddress((void**)&hid_l, g_hid_l);
    cudaGetSymbolAddress((void**)&enc_h, g_enc_h);  cudaGetSymbolAddress((void**)&enc_l, g_enc_l);
    cudaGetSymbolAddress((void**)&encT_h, g_encT_h);cudaGetSymbolAddress((void**)&encT_l, g_encT_l);
    cudaGetSymbolAddress((void**)&Wa_h, g_Wa_h);    cudaGetSymbolAddress((void**)&Wa_l, g_Wa_l);
    cudaGetSymbolAddress((void**)&Wo_h, g_Wo_h);    cudaGetSymbolAddress((void**)&Wo_l, g_Wo_l);
    cudaGetSymbolAddress((void**)&at_h, g_attn_h);  cudaGetSymbolAddress((void**)&at_l, g_attn_l);
    cudaGetSymbolAddress((void**)&wc_h, g_wc_h);    cudaGetSymbolAddress((void**)&wc_l, g_wc_l);

    cudaFuncSetAttribute(gemm128n_dual_kernel, cudaFuncAttributeMaxDynamicSharedMemorySize, GS128N);
    cudaFuncSetAttribute(gemm64_ks4_kernel,    cudaFuncAttributeMaxDynamicSharedMemorySize, GS64);

    // fused prep
    int nb0 = (B_*T_*D_)/1024, nb1 = (D_*(E_+D_))/1024, nb2 = (D_*(E_+D_))/1024;
    int ntr = (S_/32)*(E_/32)*B_;
    prep_all_kernel<<<nb0+nb1+nb2+ntr, 256>>>(
        hidden, hid_h, hid_l, nb0,
        W_attn, Wa_h,  Wa_l,  nb1,
        W_out,  Wo_h,  Wo_l,  nb2,
        enc, enc_h, enc_l, encT_h, encT_l);

    // fused hp (16 mtiles x 4 ntiles = 64) + ep (64 x 4 = 256); 64x128 tiles
    gemm128n_dual_kernel<<<64 + 256, 128, GS128N>>>(
        hid_h, hid_l, D_, Wa_h, Wa_l, E_+D_, hp, D_, b_attn, 16, 64,
        enc_h, enc_l, E_, Wa_h + D_, Wa_l + D_, E_+D_, ep, D_, 64,
        16);

    // energies
    energies_kernel<<<dim3(S_/64, T_/16, B_), 256>>>(hp, ep, W_v, b_v, mask, en);
    // softmax -> attn (+ bf16 split)
    softmax_kernel<<<dim3(B_*T_), 256>>>(en, mask, attn, at_h, at_l);

    // wc = attn @ encT^T, split-K x4 (kstep=128)
    gemm64_ks4_kernel<<<dim3(4*2, E_/64, B_), 128, GS64>>>(
        at_h, at_l, at_h, at_l, 4, 128, S_, (long long)T_*S_,
        encT_h, encT_l, S_, (long long)E_*S_,
        p0, p1, p2, p3, E_, (long long)T_*E_, 4, 2);
    combine_wc_kernel<<<(B_*T_*E_)/1024, 256>>>(p0, p1, p2, p3, wc, wc_h, wc_l);

    // h_tilde, split-K x4 at concat boundary (kstep=256)
    gemm64_ks4_kernel<<<dim3(4*16, D_/64, 1), 128, GS64>>>(
        wc_h, wc_l, hid_h, hid_l, 2, 256, E_, 0,
        Wo_h, Wo_l, E_+D_, 0,
        p0, p1, p2, p3, D_, 0, 8, 16);
    combine_ht_kernel<<<(B_*T_*D_)/1024, 256>>>(p0, p1, p2, p3, h_tilde);
}

// round 16
// speedup vs baseline: 1.0284x; 1.0284x over previous
#include <cuda_runtime.h>
#include <cuda_bf16.h>
#include <cstdint>

#define B_ 8
#define T_ 128
#define S_ 512
#define E_ 512
#define D_ 512

// ---------------- scratch (no allocs allowed) ----------------
__device__ __align__(256) float g_hp[B_*T_*D_];
__device__ __align__(256) float g_ep[B_*S_*D_];
__device__ __align__(256) float g_en[B_*T_*S_];
__device__ __align__(256) float g_p0[B_*T_*E_];   // split-K partials
__device__ __align__(256) float g_p1[B_*T_*E_];
__device__ __align__(256) float g_p2[B_*T_*E_];
__device__ __align__(256) float g_p3[B_*T_*E_];

__device__ __align__(256) __nv_bfloat16 g_hid_h[B_*T_*D_],  g_hid_l[B_*T_*D_];
__device__ __align__(256) __nv_bfloat16 g_enc_h[B_*S_*E_],  g_enc_l[B_*S_*E_];
__device__ __align__(256) __nv_bfloat16 g_encT_h[B_*E_*S_], g_encT_l[B_*E_*S_];
__device__ __align__(256) __nv_bfloat16 g_Wa_h[D_*(E_+D_)], g_Wa_l[D_*(E_+D_)];
__device__ __align__(256) __nv_bfloat16 g_Wo_h[D_*(E_+D_)], g_Wo_l[D_*(E_+D_)];
__device__ __align__(256) __nv_bfloat16 g_attn_h[B_*T_*S_], g_attn_l[B_*T_*S_];
__device__ __align__(256) __nv_bfloat16 g_wc_h[B_*T_*E_],   g_wc_l[B_*T_*E_];

__device__ __forceinline__ float tanh_fast(float x){
    float r; asm("tanh.approx.f32 %0, %1;" : "=f"(r) : "f"(x)); return r;
}
__device__ __forceinline__ uint32_t smem_u32(const void* p){
    uint32_t a;
    asm("{ .reg .u64 t; cvta.to.shared.u64 t, %1; cvt.u32.u64 %0, t; }" : "=r"(a) : "l"(p));
    return a;
}
__device__ __forceinline__ void cp16(uint32_t dst, const void* src){
    asm volatile("cp.async.cg.shared.global [%0], [%1], 16;" :: "r"(dst), "l"(src));
}
#define CP_COMMIT() asm volatile("cp.async.commit_group;" ::: "memory")
#define CP_WAIT(n)  asm volatile("cp.async.wait_group %0;" :: "n"(n) : "memory")

#define LDSM4(r, addr) \
    asm volatile("ldmatrix.sync.aligned.m8n8.x4.shared.b16 {%0,%1,%2,%3}, [%4];" \
        : "=r"((r)[0]), "=r"((r)[1]), "=r"((r)[2]), "=r"((r)[3]) : "r"(addr))

#define MMA16816(c, a, b0, b1) \
    asm volatile("mma.sync.aligned.m16n8k16.row.col.f32.bf16.bf16.f32 " \
        "{%0,%1,%2,%3}, {%4,%5,%6,%7}, {%8,%9}, {%0,%1,%2,%3};" \
        : "+f"((c)[0]), "+f"((c)[1]), "+f"((c)[2]), "+f"((c)[3]) \
        : "r"((a)[0]), "r"((a)[1]), "r"((a)[2]), "r"((a)[3]), "r"(b0), "r"(b1))

// ---------------------------------------------------------------------------
// Fused prep: fp32->bf16(hi,lo) splits for hidden/W_attn/W_out, PLUS
// enc straight-split + transposed-split.  One launch, one big balanced grid.
// ---------------------------------------------------------------------------
__global__ void prep_all_kernel(const float* __restrict__ x0, __nv_bfloat16* h0, __nv_bfloat16* l0, int b0,
                                const float* __restrict__ x1, __nv_bfloat16* h1, __nv_bfloat16* l1, int b1,
                                const float* __restrict__ x2, __nv_bfloat16* h2, __nv_bfloat16* l2, int b2,
                                const float* __restrict__ enc,
                                __nv_bfloat16* __restrict__ sh, __nv_bfloat16* __restrict__ sl,
                                __nv_bfloat16* __restrict__ th, __nv_bfloat16* __restrict__ tl)
{
    __shared__ float tile[32][33];
    int blk = blockIdx.x;
    int nsplit = b0 + b1 + b2;
    int tid = threadIdx.x;
    if (blk < nsplit){
        const float* x; __nv_bfloat16 *hi, *lo;
        if (blk < b0){ x = x0; hi = h0; lo = l0; }
        else if (blk < b0 + b1){ blk -= b0; x = x1; hi = h1; lo = l1; }
        else { blk -= b0 + b1; x = x2; hi = h2; lo = l2; }
        int i = (blk * 256 + tid) * 4;
        float4 v = *(const float4*)(x + i);
        float vv[4] = {v.x, v.y, v.z, v.w};
        __nv_bfloat16 h[4], l[4];
        #pragma unroll
        for (int j = 0; j < 4; j++){
            h[j] = __float2bfloat16_rn(vv[j]);
            l[j] = __float2bfloat16_rn(vv[j] - __bfloat162float(h[j]));
        }
        *(ushort4*)(hi + i) = *(ushort4*)h;
        *(ushort4*)(lo + i) = *(ushort4*)l;
        return;
    }
    // transpose + split of enc
    int t = blk - nsplit;
    int b = t >> 8;                 // / 256
    int rem = t & 255;
    int s0 = (rem & 15) * 32, e0 = (rem >> 4) * 32;
    int tx = tid & 31, ty = tid >> 5;
    const float* src = enc + ((size_t)b * S_ + s0) * E_ + e0;
    for (int i = ty; i < 32; i += 8){
        float v = src[(size_t)i * E_ + tx];
        tile[i][tx] = v;
        __nv_bfloat16 h = __float2bfloat16_rn(v);
        __nv_bfloat16 l = __float2bfloat16_rn(v - __bfloat162float(h));
        size_t o = ((size_t)b * S_ + s0 + i) * E_ + e0 + tx;
        sh[o] = h; sl[o] = l;
    }
    __syncthreads();
    for (int i = ty; i < 32; i += 8){
        float v = tile[tx][i];
        __nv_bfloat16 h = __float2bfloat16_rn(v);
        __nv_bfloat16 l = __float2bfloat16_rn(v - __bfloat162float(h));
        size_t o = ((size_t)b * E_ + e0 + i) * S_ + s0 + tx;
        th[o] = h; tl[o] = l;
    }
}

// ---------------------------------------------------------------------------
// 64x64 HMMA bf16-split GEMM core: 128 threads, 4 warps (2m x 2n, 32x32 each),
// BK=32, 2-stage cp.async double buffer (41KB smem -> 5 CTAs/SM).
// ---------------------------------------------------------------------------
#define RS      80
#define OFF_AL  (64*RS)
#define OFF_BH  (128*RS)
#define OFF_BL  (192*RS)
#define STG64   (256*RS)        // 20480 B
#define GS64    (2*STG64)       // 40960 B

__device__ __forceinline__ void fill64(uint32_t st,
    const __nv_bfloat16* ah, const __nv_bfloat16* al, int lda,
    const __nv_bfloat16* bh, const __nv_bfloat16* bl, int ldb, int tid)
{
    #pragma unroll
    for (int j = 0; j < 8; j++){
        int i = tid + j * 128;
        int r = i >> 2, s = i & 3, rr = r & 63;
        const __nv_bfloat16* src;
        int reg = r >> 6;
        if (reg == 0)      src = ah + (size_t)rr * lda + s * 8;
        else if (reg == 1) src = al + (size_t)rr * lda + s * 8;
        else if (reg == 2) src = bh + (size_t)rr * ldb + s * 8;
        else               src = bl + (size_t)rr * ldb + s * 8;
        cp16(st + (uint32_t)(r * RS + s * 16), src);
    }
    CP_COMMIT();
}

__device__ __forceinline__ void gemm64_core(uint32_t sb, int tid, int chunks,
    const __nv_bfloat16* ah, const __nv_bfloat16* al, int lda,
    const __nv_bfloat16* bh, const __nv_bfloat16* bl, int ldb,
    float (&acc)[2][4][4])
{
    int wid = tid >> 5, lane = tid & 31;
    int wm = (wid & 1) * 32, wn = (wid >> 1) * 32;
    int quad = lane >> 3, lr = lane & 7;
    uint32_t a_off[2], b_off[2];
    #pragma unroll
    for (int mt = 0; mt < 2; mt++)
        a_off[mt] = (uint32_t)((wm + mt*16 + (quad & 1)*8 + lr) * RS + (quad >> 1)*16);
    #pragma unroll
    for (int p = 0; p < 2; p++)
        b_off[p]  = (uint32_t)((wn + p*16 + (quad >> 1)*8 + lr) * RS + (quad & 1)*16);

    fill64(sb, ah, al, lda, bh, bl, ldb, tid);

    for (int c = 0; c < chunks; c++){
        if (c + 1 < chunks){
            int ko = (c + 1) * 32;
            fill64(sb + ((c + 1) & 1)*STG64, ah + ko, al + ko, lda, bh + ko, bl + ko, ldb, tid);
            CP_WAIT(1);
        } else {
            CP_WAIT(0);
        }
        __syncthreads();
        uint32_t st = sb + (c & 1)*STG64;
        #pragma unroll
        for (int ks = 0; ks < 2; ks++){
            uint32_t koff = ks * 32;
            uint32_t ah_[2][4], al_[2][4], bh_[2][4], bl_[2][4];
            #pragma unroll
            for (int mt = 0; mt < 2; mt++){
                LDSM4(ah_[mt], st + a_off[mt] + koff);
                LDSM4(al_[mt], st + OFF_AL + a_off[mt] + koff);
            }
            #pragma unroll
            for (int p = 0; p < 2; p++){
                LDSM4(bh_[p], st + OFF_BH + b_off[p] + koff);
                LDSM4(bl_[p], st + OFF_BL + b_off[p] + koff);
            }
            #pragma unroll
            for (int mt = 0; mt < 2; mt++)
                #pragma unroll
                for (int nt = 0; nt < 4; nt++){
                    int p = nt >> 1, q = (nt & 1) * 2;
                    MMA16816(acc[mt][nt], ah_[mt], bh_[p][q], bh_[p][q+1]);
                    MMA16816(acc[mt][nt], ah_[mt], bl_[p][q], bl_[p][q+1]);
                    MMA16816(acc[mt][nt], al_[mt], bh_[p][q], bh_[p][q+1]);
                }
        }
        __syncthreads();
    }
}

// ---- fused hp + ep launch (1D grid; job0 = hp with bias, job1 = ep) ----
__global__ void __launch_bounds__(128)
gemm64_dual_kernel(const __nv_bfloat16* __restrict__ a0h, const __nv_bfloat16* __restrict__ a0l, int lda0,
                   const __nv_bfloat16* __restrict__ b0h, const __nv_bfloat16* __restrict__ b0l, int ldb0,
                   float* __restrict__ C0, int ldc0, const float* __restrict__ bias0, int mt0, int nblk0,
                   const __nv_bfloat16* __restrict__ a1h, const __nv_bfloat16* __restrict__ a1l, int lda1,
                   const __nv_bfloat16* __restrict__ b1h, const __nv_bfloat16* __restrict__ b1l, int ldb1,
                   float* __restrict__ C1, int ldc1, int mt1,
                   int chunks)
{
    extern __shared__ __align__(16) char smem[];
    uint32_t sb = smem_u32(smem);
    int tid = threadIdx.x, bx = blockIdx.x;

    const __nv_bfloat16 *ah, *al, *bh, *bl; const float* bias;
    float* C; int lda, ldb, ldc, m0, n0;
    if (bx < nblk0){
        m0 = (bx % mt0) * 64; n0 = (bx / mt0) * 64;
        ah = a0h; al = a0l; lda = lda0; bh = b0h; bl = b0l; ldb = ldb0;
        C = C0; ldc = ldc0; bias = bias0;
    } else {
        int b2 = bx - nblk0;
        m0 = (b2 % mt1) * 64; n0 = (b2 / mt1) * 64;
        ah = a1h; al = a1l; lda = lda1; bh = b1h; bl = b1l; ldb = ldb1;
        C = C1; ldc = ldc1; bias = nullptr;
    }
    ah += (size_t)m0 * lda; al += (size_t)m0 * lda;
    bh += (size_t)n0 * ldb; bl += (size_t)n0 * ldb;

    float acc[2][4][4] = {};
    gemm64_core(sb, tid, chunks, ah, al, lda, bh, bl, ldb, acc);

    int wid = tid >> 5, lane = tid & 31;
    int wm = (wid & 1) * 32, wn = (wid >> 1) * 32;
    #pragma unroll
    for (int mt = 0; mt < 2; mt++){
        int r = m0 + wm + mt*16 + (lane >> 2);
        #pragma unroll
        for (int nt = 0; nt < 4; nt++){
            int col = n0 + wn + nt*8 + (lane & 3)*2;
            float c0 = acc[mt][nt][0], c1 = acc[mt][nt][1];
            float c2 = acc[mt][nt][2], c3 = acc[mt][nt][3];
            if (bias){
                float bb0 = bias[col], bb1 = bias[col+1];
                c0 += bb0; c1 += bb1; c2 += bb0; c3 += bb1;
            }
            *(float2*)(C + (size_t)r * ldc + col)       = make_float2(c0, c1);
            *(float2*)(C + (size_t)(r + 8) * ldc + col) = make_float2(c2, c3);
        }
    }
}

// ---- split-K (x4) batched GEMM into partial buffers P0..P3 ----
// ks = blockIdx.x / mtiles (0..3).  A source: ks < ksplitA -> A0 slice ks,
// else A1 slice (ks - ksplitA).  B offset = ks * kstep (full-K layout).
__global__ void __launch_bounds__(128)
gemm64_ks4_kernel(const __nv_bfloat16* __restrict__ A0h, const __nv_bfloat16* __restrict__ A0l,
                  const __nv_bfloat16* __restrict__ A1h, const __nv_bfloat16* __restrict__ A1l,
                  int ksplitA, int kstep, int lda, long long sA,
                  const __nv_bfloat16* __restrict__ Bh, const __nv_bfloat16* __restrict__ Bl,
                  int ldb, long long sB,
                  float* __restrict__ P0, float* __restrict__ P1,
                  float* __restrict__ P2, float* __restrict__ P3,
                  int ldp, long long sP,
                  int chunks, int mtiles)
{
    extern __shared__ __align__(16) char smem[];
    uint32_t sb = smem_u32(smem);
    int tid = threadIdx.x;
    int ks = blockIdx.x / mtiles;
    int m0 = (blockIdx.x % mtiles) * 64, n0 = blockIdx.y * 64, z = blockIdx.z;

    int second = (ks >= ksplitA);
    int kse = second ? (ks - ksplitA) : ks;
    const __nv_bfloat16* ah = (second ? A1h : A0h) + (size_t)z*sA + (size_t)m0*lda + (size_t)kse*kstep;
    const __nv_bfloat16* al = (second ? A1l : A0l) + (size_t)z*sA + (size_t)m0*lda + (size_t)kse*kstep;
    const __nv_bfloat16* bh = Bh + (size_t)z*sB + (size_t)n0*ldb + (size_t)ks*kstep;
    const __nv_bfloat16* bl = Bl + (size_t)z*sB + (size_t)n0*ldb + (size_t)ks*kstep;

    float acc[2][4][4] = {};
    gemm64_core(sb, tid, chunks, ah, al, lda, bh, bl, ldb, acc);

    float* P = (ks == 0 ? P0 : ks == 1 ? P1 : ks == 2 ? P2 : P3) + (size_t)z * sP;
    int wid = tid >> 5, lane = tid & 31;
    int wm = (wid & 1) * 32, wn = (wid >> 1) * 32;
    #pragma unroll
    for (int mt = 0; mt < 2; mt++){
        int r = m0 + wm + mt*16 + (lane >> 2);
        #pragma unroll
        for (int nt = 0; nt < 4; nt++){
            int col = n0 + wn + nt*8 + (lane & 3)*2;
            *(float2*)(P + (size_t)r * ldp + col)       = make_float2(acc[mt][nt][0], acc[mt][nt][1]);
            *(float2*)(P + (size_t)(r + 8) * ldp + col) = make_float2(acc[mt][nt][2], acc[mt][nt][3]);
        }
    }
}

// ---- combine 4 partials: wc = sum (also bf16 split); ht = tanh(sum) ----
__global__ void combine_wc_kernel(const float* __restrict__ p0, const float* __restrict__ p1,
                                  const float* __restrict__ p2, const float* __restrict__ p3,
                                  float* __restrict__ wc,
                                  __nv_bfloat16* __restrict__ ch, __nv_bfloat16* __restrict__ cl)
{
    int i = (blockIdx.x * 256 + threadIdx.x) * 4;
    float4 a = *(const float4*)(p0 + i);
    float4 b = *(const float4*)(p1 + i);
    float4 c = *(const float4*)(p2 + i);
    float4 d = *(const float4*)(p3 + i);
    float v[4] = {((a.x + b.x) + c.x) + d.x, ((a.y + b.y) + c.y) + d.y,
                  ((a.z + b.z) + c.z) + d.z, ((a.w + b.w) + c.w) + d.w};
    *(float4*)(wc + i) = make_float4(v[0], v[1], v[2], v[3]);
    __nv_bfloat16 h[4], l[4];
    #pragma unroll
    for (int j = 0; j < 4; j++){
        h[j] = __float2bfloat16_rn(v[j]);
        l[j] = __float2bfloat16_rn(v[j] - __bfloat162float(h[j]));
    }
    *(ushort4*)(ch + i) = *(ushort4*)h;
    *(ushort4*)(cl + i) = *(ushort4*)l;
}

__global__ void combine_ht_kernel(const float* __restrict__ p0, const float* __restrict__ p1,
                                  const float* __restrict__ p2, const float* __restrict__ p3,
                                  float* __restrict__ ht)
{
    int i = (blockIdx.x * 256 + threadIdx.x) * 4;
    float4 a = *(const float4*)(p0 + i);
    float4 b = *(const float4*)(p1 + i);
    float4 c = *(const float4*)(p2 + i);
    float4 d = *(const float4*)(p3 + i);
    *(float4*)(ht + i) = make_float4(tanh_fast(((a.x + b.x) + c.x) + d.x),
                                     tanh_fast(((a.y + b.y) + c.y) + d.y),
                                     tanh_fast(((a.z + b.z) + c.z) + d.z),
                                     tanh_fast(((a.w + b.w) + c.w) + d.w));
}

// ---------------------------------------------------------------------------
// energies[b,t,s] = ( sum_k W_v[k]*tanh(hp[b,t,k] + ep[b,s,k]) + b_v ) * m[b,s]
// R9/R7 proven structure: 16t x 64s, BK=32, single smem buffer, register
// prefetch of the next chunk's LDG overlapping the MUFU compute.
// ---------------------------------------------------------------------------
__global__ void energies_kernel(const float* __restrict__ hp,
                                const float* __restrict__ ep,
                                const float* __restrict__ wv,
                                const float* __restrict__ bv,
                                const float* __restrict__ mask,
                                float* __restrict__ en)
{
    __shared__ __align__(16) float hps[32][17];
    __shared__ __align__(16) float eps[32][65];
    __shared__ float wvs[32];
    int b = blockIdx.z, t0 = blockIdx.y * 16, s0 = blockIdx.x * 64;
    int tid = threadIdx.x;
    int sx = tid & 31, ty = tid >> 5;
    const float* hpb = hp + (size_t)(b*T_ + t0) * D_;
    const float* epb = ep + (size_t)(b*S_ + s0) * D_;
    float a00=0.f, a01=0.f, a10=0.f, a11=0.f;
    int ht = tid >> 4, hk = (tid & 15) << 1;
    int es = tid >> 2, ek = (tid & 3) << 3;

    // prefetch chunk 0
    float2 hv = *(const float2*)(hpb + (size_t)ht*D_ + hk);
    float4 e0v = *(const float4*)(epb + (size_t)es*D_ + ek);
    float4 e1v = *(const float4*)(epb + (size_t)es*D_ + ek + 4);
    float wvv = (tid < 32) ? wv[tid] : 0.f;

    for (int k0 = 0; k0 < D_; k0 += 32) {
        hps[hk][ht] = hv.x; hps[hk+1][ht] = hv.y;
        eps[ek+0][es]=e0v.x; eps[ek+1][es]=e0v.y; eps[ek+2][es]=e0v.z; eps[ek+3][es]=e0v.w;
        eps[ek+4][es]=e1v.x; eps[ek+5][es]=e1v.y; eps[ek+6][es]=e1v.z; eps[ek+7][es]=e1v.w;
        if (tid < 32) wvs[tid] = wvv;
        __syncthreads();
        if (k0 + 32 < D_){
            int kn = k0 + 32;
            hv  = *(const float2*)(hpb + (size_t)ht*D_ + kn + hk);
            e0v = *(const float4*)(epb + (size_t)es*D_ + kn + ek);
            e1v = *(const float4*)(epb + (size_t)es*D_ + kn + ek + 4);
            if (tid < 32) wvv = wv[kn + tid];
        }
        #pragma unroll
        for (int k = 0; k < 32; k++) {
            float w  = wvs[k];
            float h0 = hps[k][ty], h1 = hps[k][ty+8];
            float e0 = eps[k][sx], e1 = eps[k][sx+32];
            a00 = fmaf(w, tanh_fast(h0+e0), a00);
            a01 = fmaf(w, tanh_fast(h0+e1), a01);
            a10 = fmaf(w, tanh_fast(h1+e0), a10);
            a11 = fmaf(w, tanh_fast(h1+e1), a11);
        }
        __syncthreads();
    }
    float bb  = bv[0];
    float mv0 = mask[(size_t)b*S_ + s0 + sx];
    float mv1 = mask[(size_t)b*S_ + s0 + sx + 32];
    size_t r0 = (size_t)(b*T_ + t0 + ty)     * S_ + s0;
    size_t r1 = (size_t)(b*T_ + t0 + ty + 8) * S_ + s0;
    en[r0 + sx]      = (a00 + bb) * mv0;
    en[r0 + sx + 32] = (a01 + bb) * mv1;
    en[r1 + sx]      = (a10 + bb) * mv0;
    en[r1 + sx + 32] = (a11 + bb) * mv1;
}

// ---------------------------------------------------------------------------
// masked softmax + bf16 split of attn weights
// ---------------------------------------------------------------------------
__global__ void softmax_kernel(const float* __restrict__ en,
                               const float* __restrict__ mask,
                               float* __restrict__ attn,
                               __nv_bfloat16* __restrict__ ah,
                               __nv_bfloat16* __restrict__ al)
{
    int r = blockIdx.x;
    int b = r >> 7;
    const float* e = en + (size_t)r * S_;
    const float* m = mask + (size_t)b * S_;
    int tid = threadIdx.x;
    float m0v = m[tid], m1v = m[tid + 256];
    float x0 = e[tid] * m0v, x1 = e[tid + 256] * m1v;
    float mx = fmaxf(x0, x1);
    #pragma unroll
    for (int o = 16; o; o >>= 1) mx = fmaxf(mx, __shfl_xor_sync(0xffffffffu, mx, o));
    __shared__ float red[8];
    int w = tid >> 5, l = tid & 31;
    if (l == 0) red[w] = mx;
    __syncthreads();
    mx = red[0];
    #pragma unroll
    for (int i = 1; i < 8; i++) mx = fmaxf(mx, red[i]);
    float e0 = __expf(x0 - mx) * m0v;
    float e1 = __expf(x1 - mx) * m1v;
    float s = e0 + e1;
    #pragma unroll
    for (int o = 16; o; o >>= 1) s += __shfl_xor_sync(0xffffffffu, s, o);
    __syncthreads();
    if (l == 0) red[w] = s;
    __syncthreads();
    float tot = 0.f;
    #pragma unroll
    for (int i = 0; i < 8; i++) tot += red[i];
    float inv = 1.0f / (tot + 1e-6f);
    float a0 = e0 * inv, a1 = e1 * inv;
    size_t base = (size_t)r * S_;
    attn[base + tid]       = a0;
    attn[base + tid + 256] = a1;
    __nv_bfloat16 h0 = __float2bfloat16_rn(a0);
    __nv_bfloat16 h1 = __float2bfloat16_rn(a1);
    ah[base + tid]       = h0;
    ah[base + tid + 256] = h1;
    al[base + tid]       = __float2bfloat16_rn(a0 - __bfloat162float(h0));
    al[base + tid + 256] = __float2bfloat16_rn(a1 - __bfloat162float(h1));
}

// ---------------------------------------------------------------------------
extern "C" void kernel_launch(void* const* d_in, const int* in_sizes, int n_in,
                              void* d_out, int out_size)
{
    const float* hidden = (const float*)d_in[0];
    const float* enc    = (const float*)d_in[1];
    const float* mask   = (const float*)d_in[2];
    const float* W_attn = (const float*)d_in[3];
    const float* b_attn = (const float*)d_in[4];
    const float* W_v    = (const float*)d_in[5];
    const float* b_v    = (const float*)d_in[6];
    const float* W_out  = (const float*)d_in[7];

    float* out     = (float*)d_out;
    float* h_tilde = out;
    float* wc      = out + (size_t)B_*T_*D_;
    float* attn    = wc  + (size_t)B_*T_*E_;

    float *hp, *ep, *en, *p0, *p1, *p2, *p3;
    cudaGetSymbolAddress((void**)&hp, g_hp);
    cudaGetSymbolAddress((void**)&ep, g_ep);
    cudaGetSymbolAddress((void**)&en, g_en);
    cudaGetSymbolAddress((void**)&p0, g_p0);
    cudaGetSymbolAddress((void**)&p1, g_p1);
    cudaGetSymbolAddress((void**)&p2, g_p2);
    cudaGetSymbolAddress((void**)&p3, g_p3);
    __nv_bfloat16 *hid_h,*hid_l,*enc_h,*enc_l,*encT_h,*encT_l,*Wa_h,*Wa_l,*Wo_h,*Wo_l,*at_h,*at_l,*wc_h,*wc_l;
    cudaGetSymbolAddress((void**)&hid_h, g_hid_h);  cudaGetSymbolAddress((void**)&hid_l, g_hid_l);
    cudaGetSymbolAddress((void**)&enc_h, g_enc_h);  cudaGetSymbolAddress((void**)&enc_l, g_enc_l);
    cudaGetSymbolAddress((void**)&encT_h, g_encT_h);cudaGetSymbolAddress((void**)&encT_l, g_encT_l);
    cudaGetSymbolAddress((void**)&Wa_h, g_Wa_h);    cudaGetSymbolAddress((void**)&Wa_l, g_Wa_l);
    cudaGetSymbolAddress((void**)&Wo_h, g_Wo_h);    cudaGetSymbolAddress((void**)&Wo_l, g_Wo_l);
    cudaGetSymbolAddress((void**)&at_h, g_attn_h);  cudaGetSymbolAddress((void**)&at_l, g_attn_l);
    cudaGetSymbolAddress((void**)&wc_h, g_wc_h);    cudaGetSymbolAddress((void**)&wc_l, g_wc_l);

    cudaFuncSetAttribute(gemm64_dual_kernel, cudaFuncAttributeMaxDynamicSharedMemorySize, GS64);
    cudaFuncSetAttribute(gemm64_ks4_kernel,  cudaFuncAttributeMaxDynamicSharedMemorySize, GS64);

    // fused prep: hidden/W_attn/W_out splits + enc split/transpose-split
    int nb0 = (B_*T_*D_)/1024, nb1 = (D_*(E_+D_))/1024, nb2 = (D_*(E_+D_))/1024;
    int ntr = (S_/32)*(E_/32)*B_;   // 2048 transpose blocks
    prep_all_kernel<<<nb0+nb1+nb2+ntr, 256>>>(
        hidden, hid_h, hid_l, nb0,
        W_attn, Wa_h,  Wa_l,  nb1,
        W_out,  Wo_h,  Wo_l,  nb2,
        enc, enc_h, enc_l, encT_h, encT_l);

    // fused hp (job0: M=1024, 16 mtiles) + ep (job1: M=4096, 64 mtiles); N=512, K=512
    gemm64_dual_kernel<<<128 + 512, 128, GS64>>>(
        hid_h, hid_l, D_, Wa_h, Wa_l, E_+D_, hp, D_, b_attn, 16, 128,
        enc_h, enc_l, E_, Wa_h + D_, Wa_l + D_, E_+D_, ep, D_, 64,
        16);

    // energies: 16t x 64s tiles, BK=32 (proven config)
    energies_kernel<<<dim3(S_/64, T_/16, B_), 256>>>(hp, ep, W_v, b_v, mask, en);
    // softmax -> attn (+ bf16 split)
    softmax_kernel<<<dim3(B_*T_), 256>>>(en, mask, attn, at_h, at_l);

    // wc = attn @ encT^T (batched, M=128, N=512, K=512), split-K x4 (kstep=128)
    gemm64_ks4_kernel<<<dim3(4*2, E_/64, B_), 128, GS64>>>(
        at_h, at_l, at_h, at_l, 4, 128, S_, (long long)T_*S_,
        encT_h, encT_l, S_, (long long)E_*S_,
        p0, p1, p2, p3, E_, (long long)T_*E_, 4, 2);
    combine_wc_kernel<<<(B_*T_*E_)/1024, 256>>>(p0, p1, p2, p3, wc, wc_h, wc_l);

    // h_tilde = tanh(concat(wc, hidden) @ W_out^T), split-K x4:
    // ks 0,1 -> wc slices (kstep=256); ks 2,3 -> hidden slices.  B offset = ks*256.
    gemm64_ks4_kernel<<<dim3(4*16, D_/64, 1), 128, GS64>>>(
        wc_h, wc_l, hid_h, hid_l, 2, 256, E_, 0,
        Wo_h, Wo_l, E_+D_, 0,
        p0, p1, p2, p3, D_, 0, 8, 16);
    combine_ht_kernel<<<(B_*T_*D_)/1024, 256>>>(p0, p1, p2, p3, h_tilde);
}

// round 17
// speedup vs baseline: 1.0305x; 1.0020x over previous
#include <cuda_runtime.h>
#include <cuda_bf16.h>
#include <cstdint>

#define B_ 8
#define T_ 128
#define S_ 512
#define E_ 512
#define D_ 512

// ---------------- scratch (no allocs allowed) ----------------
__device__ __align__(256) float g_hp[B_*T_*D_];
__device__ __align__(256) float g_ep[B_*S_*D_];
__device__ __align__(256) float g_en[B_*T_*S_];
__device__ __align__(256) float g_p0[B_*T_*E_];   // split-K partials
__device__ __align__(256) float g_p1[B_*T_*E_];
__device__ __align__(256) float g_p2[B_*T_*E_];
__device__ __align__(256) float g_p3[B_*T_*E_];

__device__ __align__(256) __nv_bfloat16 g_hid_h[B_*T_*D_],  g_hid_l[B_*T_*D_];
__device__ __align__(256) __nv_bfloat16 g_enc_h[B_*S_*E_],  g_enc_l[B_*S_*E_];
__device__ __align__(256) __nv_bfloat16 g_encT_h[B_*E_*S_], g_encT_l[B_*E_*S_];
__device__ __align__(256) __nv_bfloat16 g_Wa_h[D_*(E_+D_)], g_Wa_l[D_*(E_+D_)];
__device__ __align__(256) __nv_bfloat16 g_Wo_h[D_*(E_+D_)], g_Wo_l[D_*(E_+D_)];
__device__ __align__(256) __nv_bfloat16 g_attn_h[B_*T_*S_], g_attn_l[B_*T_*S_];
__device__ __align__(256) __nv_bfloat16 g_wc_h[B_*T_*E_],   g_wc_l[B_*T_*E_];

__device__ __forceinline__ float tanh_fast(float x){
    float r; asm("tanh.approx.f32 %0, %1;" : "=f"(r) : "f"(x)); return r;
}
__device__ __forceinline__ uint32_t smem_u32(const void* p){
    uint32_t a;
    asm("{ .reg .u64 t; cvta.to.shared.u64 t, %1; cvt.u32.u64 %0, t; }" : "=r"(a) : "l"(p));
    return a;
}
__device__ __forceinline__ void cp16(uint32_t dst, const void* src){
    asm volatile("cp.async.cg.shared.global [%0], [%1], 16;" :: "r"(dst), "l"(src));
}
#define CP_COMMIT() asm volatile("cp.async.commit_group;" ::: "memory")
#define CP_WAIT(n)  asm volatile("cp.async.wait_group %0;" :: "n"(n) : "memory")

#define LDSM4(r, addr) \
    asm volatile("ldmatrix.sync.aligned.m8n8.x4.shared.b16 {%0,%1,%2,%3}, [%4];" \
        : "=r"((r)[0]), "=r"((r)[1]), "=r"((r)[2]), "=r"((r)[3]) : "r"(addr))

#define MMA16816(c, a, b0, b1) \
    asm volatile("mma.sync.aligned.m16n8k16.row.col.f32.bf16.bf16.f32 " \
        "{%0,%1,%2,%3}, {%4,%5,%6,%7}, {%8,%9}, {%0,%1,%2,%3};" \
        : "+f"((c)[0]), "+f"((c)[1]), "+f"((c)[2]), "+f"((c)[3]) \
        : "r"((a)[0]), "r"((a)[1]), "r"((a)[2]), "r"((a)[3]), "r"(b0), "r"(b1))

// ---------------------------------------------------------------------------
// Fused prep: fp32->bf16(hi,lo) splits for hidden/W_attn/W_out, PLUS
// enc straight-split + transposed-split.  One launch, one big balanced grid.
// ---------------------------------------------------------------------------
__global__ void prep_all_kernel(const float* __restrict__ x0, __nv_bfloat16* h0, __nv_bfloat16* l0, int b0,
                                const float* __restrict__ x1, __nv_bfloat16* h1, __nv_bfloat16* l1, int b1,
                                const float* __restrict__ x2, __nv_bfloat16* h2, __nv_bfloat16* l2, int b2,
                                const float* __restrict__ enc,
                                __nv_bfloat16* __restrict__ sh, __nv_bfloat16* __restrict__ sl,
                                __nv_bfloat16* __restrict__ th, __nv_bfloat16* __restrict__ tl)
{
    __shared__ float tile[32][33];
    int blk = blockIdx.x;
    int nsplit = b0 + b1 + b2;
    int tid = threadIdx.x;
    if (blk < nsplit){
        const float* x; __nv_bfloat16 *hi, *lo;
        if (blk < b0){ x = x0; hi = h0; lo = l0; }
        else if (blk < b0 + b1){ blk -= b0; x = x1; hi = h1; lo = l1; }
        else { blk -= b0 + b1; x = x2; hi = h2; lo = l2; }
        int i = (blk * 256 + tid) * 4;
        float4 v = *(const float4*)(x + i);
        float vv[4] = {v.x, v.y, v.z, v.w};
        __nv_bfloat16 h[4], l[4];
        #pragma unroll
        for (int j = 0; j < 4; j++){
            h[j] = __float2bfloat16_rn(vv[j]);
            l[j] = __float2bfloat16_rn(vv[j] - __bfloat162float(h[j]));
        }
        *(ushort4*)(hi + i) = *(ushort4*)h;
        *(ushort4*)(lo + i) = *(ushort4*)l;
        return;
    }
    // transpose + split of enc
    int t = blk - nsplit;
    int b = t >> 8;                 // / 256
    int rem = t & 255;
    int s0 = (rem & 15) * 32, e0 = (rem >> 4) * 32;
    int tx = tid & 31, ty = tid >> 5;
    const float* src = enc + ((size_t)b * S_ + s0) * E_ + e0;
    for (int i = ty; i < 32; i += 8){
        float v = src[(size_t)i * E_ + tx];
        tile[i][tx] = v;
        __nv_bfloat16 h = __float2bfloat16_rn(v);
        __nv_bfloat16 l = __float2bfloat16_rn(v - __bfloat162float(h));
        size_t o = ((size_t)b * S_ + s0 + i) * E_ + e0 + tx;
        sh[o] = h; sl[o] = l;
    }
    __syncthreads();
    for (int i = ty; i < 32; i += 8){
        float v = tile[tx][i];
        __nv_bfloat16 h = __float2bfloat16_rn(v);
        __nv_bfloat16 l = __float2bfloat16_rn(v - __bfloat162float(h));
        size_t o = ((size_t)b * E_ + e0 + i) * S_ + s0 + tx;
        th[o] = h; tl[o] = l;
    }
}

// ---------------------------------------------------------------------------
// 64x64 HMMA bf16-split GEMM core: 128 threads, 4 warps (2m x 2n, 32x32 each),
// BK=32, 2-stage cp.async double buffer (41KB smem -> 5 CTAs/SM).
// ---------------------------------------------------------------------------
#define RS      80
#define OFF_AL  (64*RS)
#define OFF_BH  (128*RS)
#define OFF_BL  (192*RS)
#define STG64   (256*RS)        // 20480 B
#define GS64    (2*STG64)       // 40960 B

__device__ __forceinline__ void fill64(uint32_t st,
    const __nv_bfloat16* ah, const __nv_bfloat16* al, int lda,
    const __nv_bfloat16* bh, const __nv_bfloat16* bl, int ldb, int tid)
{
    #pragma unroll
    for (int j = 0; j < 8; j++){
        int i = tid + j * 128;
        int r = i >> 2, s = i & 3, rr = r & 63;
        const __nv_bfloat16* src;
        int reg = r >> 6;
        if (reg == 0)      src = ah + (size_t)rr * lda + s * 8;
        else if (reg == 1) src = al + (size_t)rr * lda + s * 8;
        else if (reg == 2) src = bh + (size_t)rr * ldb + s * 8;
        else               src = bl + (size_t)rr * ldb + s * 8;
        cp16(st + (uint32_t)(r * RS + s * 16), src);
    }
    CP_COMMIT();
}

__device__ __forceinline__ void gemm64_core(uint32_t sb, int tid, int chunks,
    const __nv_bfloat16* ah, const __nv_bfloat16* al, int lda,
    const __nv_bfloat16* bh, const __nv_bfloat16* bl, int ldb,
    float (&acc)[2][4][4])
{
    int wid = tid >> 5, lane = tid & 31;
    int wm = (wid & 1) * 32, wn = (wid >> 1) * 32;
    int quad = lane >> 3, lr = lane & 7;
    uint32_t a_off[2], b_off[2];
    #pragma unroll
    for (int mt = 0; mt < 2; mt++)
        a_off[mt] = (uint32_t)((wm + mt*16 + (quad & 1)*8 + lr) * RS + (quad >> 1)*16);
    #pragma unroll
    for (int p = 0; p < 2; p++)
        b_off[p]  = (uint32_t)((wn + p*16 + (quad >> 1)*8 + lr) * RS + (quad & 1)*16);

    fill64(sb, ah, al, lda, bh, bl, ldb, tid);

    for (int c = 0; c < chunks; c++){
        if (c + 1 < chunks){
            int ko = (c + 1) * 32;
            fill64(sb + ((c + 1) & 1)*STG64, ah + ko, al + ko, lda, bh + ko, bl + ko, ldb, tid);
            CP_WAIT(1);
        } else {
            CP_WAIT(0);
        }
        __syncthreads();
        uint32_t st = sb + (c & 1)*STG64;
        #pragma unroll
        for (int ks = 0; ks < 2; ks++){
            uint32_t koff = ks * 32;
            uint32_t ah_[2][4], al_[2][4], bh_[2][4], bl_[2][4];
            #pragma unroll
            for (int mt = 0; mt < 2; mt++){
                LDSM4(ah_[mt], st + a_off[mt] + koff);
                LDSM4(al_[mt], st + OFF_AL + a_off[mt] + koff);
            }
            #pragma unroll
            for (int p = 0; p < 2; p++){
                LDSM4(bh_[p], st + OFF_BH + b_off[p] + koff);
                LDSM4(bl_[p], st + OFF_BL + b_off[p] + koff);
            }
            #pragma unroll
            for (int mt = 0; mt < 2; mt++)
                #pragma unroll
                for (int nt = 0; nt < 4; nt++){
                    int p = nt >> 1, q = (nt & 1) * 2;
                    MMA16816(acc[mt][nt], ah_[mt], bh_[p][q], bh_[p][q+1]);
                    MMA16816(acc[mt][nt], ah_[mt], bl_[p][q], bl_[p][q+1]);
                    MMA16816(acc[mt][nt], al_[mt], bh_[p][q], bh_[p][q+1]);
                }
        }
        __syncthreads();
    }
}

// ---- fused hp + ep launch (1D grid; job0 = hp with bias, job1 = ep) ----
__global__ void __launch_bounds__(128)
gemm64_dual_kernel(const __nv_bfloat16* __restrict__ a0h, const __nv_bfloat16* __restrict__ a0l, int lda0,
                   const __nv_bfloat16* __restrict__ b0h, const __nv_bfloat16* __restrict__ b0l, int ldb0,
                   float* __restrict__ C0, int ldc0, const float* __restrict__ bias0, int mt0, int nblk0,
                   const __nv_bfloat16* __restrict__ a1h, const __nv_bfloat16* __restrict__ a1l, int lda1,
                   const __nv_bfloat16* __restrict__ b1h, const __nv_bfloat16* __restrict__ b1l, int ldb1,
                   float* __restrict__ C1, int ldc1, int mt1,
                   int chunks)
{
    extern __shared__ __align__(16) char smem[];
    uint32_t sb = smem_u32(smem);
    int tid = threadIdx.x, bx = blockIdx.x;

    const __nv_bfloat16 *ah, *al, *bh, *bl; const float* bias;
    float* C; int lda, ldb, ldc, m0, n0;
    if (bx < nblk0){
        m0 = (bx % mt0) * 64; n0 = (bx / mt0) * 64;
        ah = a0h; al = a0l; lda = lda0; bh = b0h; bl = b0l; ldb = ldb0;
        C = C0; ldc = ldc0; bias = bias0;
    } else {
        int b2 = bx - nblk0;
        m0 = (b2 % mt1) * 64; n0 = (b2 / mt1) * 64;
        ah = a1h; al = a1l; lda = lda1; bh = b1h; bl = b1l; ldb = ldb1;
        C = C1; ldc = ldc1; bias = nullptr;
    }
    ah += (size_t)m0 * lda; al += (size_t)m0 * lda;
    bh += (size_t)n0 * ldb; bl += (size_t)n0 * ldb;

    float acc[2][4][4] = {};
    gemm64_core(sb, tid, chunks, ah, al, lda, bh, bl, ldb, acc);

    int wid = tid >> 5, lane = tid & 31;
    int wm = (wid & 1) * 32, wn = (wid >> 1) * 32;
    #pragma unroll
    for (int mt = 0; mt < 2; mt++){
        int r = m0 + wm + mt*16 + (lane >> 2);
        #pragma unroll
        for (int nt = 0; nt < 4; nt++){
            int col = n0 + wn + nt*8 + (lane & 3)*2;
            float c0 = acc[mt][nt][0], c1 = acc[mt][nt][1];
            float c2 = acc[mt][nt][2], c3 = acc[mt][nt][3];
            if (bias){
                float bb0 = bias[col], bb1 = bias[col+1];
                c0 += bb0; c1 += bb1; c2 += bb0; c3 += bb1;
            }
            *(float2*)(C + (size_t)r * ldc + col)       = make_float2(c0, c1);
            *(float2*)(C + (size_t)(r + 8) * ldc + col) = make_float2(c2, c3);
        }
    }
}

// ---- split-K (x4) batched GEMM into partial buffers P0..P3 ----
__global__ void __launch_bounds__(128)
gemm64_ks4_kernel(const __nv_bfloat16* __restrict__ A0h, const __nv_bfloat16* __restrict__ A0l,
                  const __nv_bfloat16* __restrict__ A1h, const __nv_bfloat16* __restrict__ A1l,
                  int ksplitA, int kstep, int lda, long long sA,
                  const __nv_bfloat16* __restrict__ Bh, const __nv_bfloat16* __restrict__ Bl,
                  int ldb, long long sB,
                  float* __restrict__ P0, float* __restrict__ P1,
                  float* __restrict__ P2, float* __restrict__ P3,
                  int ldp, long long sP,
                  int chunks, int mtiles)
{
    extern __shared__ __align__(16) char smem[];
    uint32_t sb = smem_u32(smem);
    int tid = threadIdx.x;
    int ks = blockIdx.x / mtiles;
    int m0 = (blockIdx.x % mtiles) * 64, n0 = blockIdx.y * 64, z = blockIdx.z;

    int second = (ks >= ksplitA);
    int kse = second ? (ks - ksplitA) : ks;
    const __nv_bfloat16* ah = (second ? A1h : A0h) + (size_t)z*sA + (size_t)m0*lda + (size_t)kse*kstep;
    const __nv_bfloat16* al = (second ? A1l : A0l) + (size_t)z*sA + (size_t)m0*lda + (size_t)kse*kstep;
    const __nv_bfloat16* bh = Bh + (size_t)z*sB + (size_t)n0*ldb + (size_t)ks*kstep;
    const __nv_bfloat16* bl = Bl + (size_t)z*sB + (size_t)n0*ldb + (size_t)ks*kstep;

    float acc[2][4][4] = {};
    gemm64_core(sb, tid, chunks, ah, al, lda, bh, bl, ldb, acc);

    float* P = (ks == 0 ? P0 : ks == 1 ? P1 : ks == 2 ? P2 : P3) + (size_t)z * sP;
    int wid = tid >> 5, lane = tid & 31;
    int wm = (wid & 1) * 32, wn = (wid >> 1) * 32;
    #pragma unroll
    for (int mt = 0; mt < 2; mt++){
        int r = m0 + wm + mt*16 + (lane >> 2);
        #pragma unroll
        for (int nt = 0; nt < 4; nt++){
            int col = n0 + wn + nt*8 + (lane & 3)*2;
            *(float2*)(P + (size_t)r * ldp + col)       = make_float2(acc[mt][nt][0], acc[mt][nt][1]);
            *(float2*)(P + (size_t)(r + 8) * ldp + col) = make_float2(acc[mt][nt][2], acc[mt][nt][3]);
        }
    }
}

// ---- combine 4 partials: wc = sum (also bf16 split); ht = tanh(sum) ----
__global__ void combine_wc_kernel(const float* __restrict__ p0, const float* __restrict__ p1,
                                  const float* __restrict__ p2, const float* __restrict__ p3,
                                  float* __restrict__ wc,
                                  __nv_bfloat16* __restrict__ ch, __nv_bfloat16* __restrict__ cl)
{
    int i = (blockIdx.x * 256 + threadIdx.x) * 4;
    float4 a = *(const float4*)(p0 + i);
    float4 b = *(const float4*)(p1 + i);
    float4 c = *(const float4*)(p2 + i);
    float4 d = *(const float4*)(p3 + i);
    float v[4] = {((a.x + b.x) + c.x) + d.x, ((a.y + b.y) + c.y) + d.y,
                  ((a.z + b.z) + c.z) + d.z, ((a.w + b.w) + c.w) + d.w};
    *(float4*)(wc + i) = make_float4(v[0], v[1], v[2], v[3]);
    __nv_bfloat16 h[4], l[4];
    #pragma unroll
    for (int j = 0; j < 4; j++){
        h[j] = __float2bfloat16_rn(v[j]);
        l[j] = __float2bfloat16_rn(v[j] - __bfloat162float(h[j]));
    }
    *(ushort4*)(ch + i) = *(ushort4*)h;
    *(ushort4*)(cl + i) = *(ushort4*)l;
}

__global__ void combine_ht_kernel(const float* __restrict__ p0, const float* __restrict__ p1,
                                  const float* __restrict__ p2, const float* __restrict__ p3,
                                  float* __restrict__ ht)
{
    int i = (blockIdx.x * 256 + threadIdx.x) * 4;
    float4 a = *(const float4*)(p0 + i);
    float4 b = *(const float4*)(p1 + i);
    float4 c = *(const float4*)(p2 + i);
    float4 d = *(const float4*)(p3 + i);
    *(float4*)(ht + i) = make_float4(tanh_fast(((a.x + b.x) + c.x) + d.x),
                                     tanh_fast(((a.y + b.y) + c.y) + d.y),
                                     tanh_fast(((a.z + b.z) + c.z) + d.z),
                                     tanh_fast(((a.w + b.w) + c.w) + d.w));
}

// ---------------------------------------------------------------------------
// energies[b,t,s] = ( sum_k W_v[k]*tanh(hp[b,t,k] + ep[b,s,k]) + b_v ) * m[b,s]
// R9/R7 proven structure: 16t x 64s, BK=32, single smem buffer, register
// prefetch of the next chunk's LDG overlapping the MUFU compute.
// ---------------------------------------------------------------------------
__global__ void energies_kernel(const float* __restrict__ hp,
                                const float* __restrict__ ep,
                                const float* __restrict__ wv,
                                const float* __restrict__ bv,
                                const float* __restrict__ mask,
                                float* __restrict__ en)
{
    __shared__ __align__(16) float hps[32][17];
    __shared__ __align__(16) float eps[32][65];
    __shared__ float wvs[32];
    int b = blockIdx.z, t0 = blockIdx.y * 16, s0 = blockIdx.x * 64;
    int tid = threadIdx.x;
    int sx = tid & 31, ty = tid >> 5;
    const float* hpb = hp + (size_t)(b*T_ + t0) * D_;
    const float* epb = ep + (size_t)(b*S_ + s0) * D_;
    float a00=0.f, a01=0.f, a10=0.f, a11=0.f;
    int ht = tid >> 4, hk = (tid & 15) << 1;
    int es = tid >> 2, ek = (tid & 3) << 3;

    // prefetch chunk 0
    float2 hv = *(const float2*)(hpb + (size_t)ht*D_ + hk);
    float4 e0v = *(const float4*)(epb + (size_t)es*D_ + ek);
    float4 e1v = *(const float4*)(epb + (size_t)es*D_ + ek + 4);
    float wvv = (tid < 32) ? wv[tid] : 0.f;

    for (int k0 = 0; k0 < D_; k0 += 32) {
        hps[hk][ht] = hv.x; hps[hk+1][ht] = hv.y;
        eps[ek+0][es]=e0v.x; eps[ek+1][es]=e0v.y; eps[ek+2][es]=e0v.z; eps[ek+3][es]=e0v.w;
        eps[ek+4][es]=e1v.x; eps[ek+5][es]=e1v.y; eps[ek+6][es]=e1v.z; eps[ek+7][es]=e1v.w;
        if (tid < 32) wvs[tid] = wvv;
        __syncthreads();
        if (k0 + 32 < D_){
            int kn = k0 + 32;
            hv  = *(const float2*)(hpb + (size_t)ht*D_ + kn + hk);
            e0v = *(const float4*)(epb + (size_t)es*D_ + kn + ek);
            e1v = *(const float4*)(epb + (size_t)es*D_ + kn + ek + 4);
            if (tid < 32) wvv = wv[kn + tid];
        }
        #pragma unroll
        for (int k = 0; k < 32; k++) {
            float w  = wvs[k];
            float h0 = hps[k][ty], h1 = hps[k][ty+8];
            float e0 = eps[k][sx], e1 = eps[k][sx+32];
            a00 = fmaf(w, tanh_fast(h0+e0), a00);
            a01 = fmaf(w, tanh_fast(h0+e1), a01);
            a10 = fmaf(w, tanh_fast(h1+e0), a10);
            a11 = fmaf(w, tanh_fast(h1+e1), a11);
        }
        __syncthreads();
    }
    float bb  = bv[0];
    float mv0 = mask[(size_t)b*S_ + s0 + sx];
    float mv1 = mask[(size_t)b*S_ + s0 + sx + 32];
    size_t r0 = (size_t)(b*T_ + t0 + ty)     * S_ + s0;
    size_t r1 = (size_t)(b*T_ + t0 + ty + 8) * S_ + s0;
    en[r0 + sx]      = (a00 + bb) * mv0;
    en[r0 + sx + 32] = (a01 + bb) * mv1;
    en[r1 + sx]      = (a10 + bb) * mv0;
    en[r1 + sx + 32] = (a11 + bb) * mv1;
}

// ---------------------------------------------------------------------------
// masked softmax + bf16 split: ONE WARP PER ROW (no block barriers, no smem).
// 8 warps/block, 16 elems/lane via 4 coalesced float4 loads, shuffle reductions.
// ---------------------------------------------------------------------------
__global__ void __launch_bounds__(256)
softmax_kernel(const float* __restrict__ en,
               const float* __restrict__ mask,
               float* __restrict__ attn,
               __nv_bfloat16* __restrict__ ah,
               __nv_bfloat16* __restrict__ al)
{
    int wid  = threadIdx.x >> 5, lane = threadIdx.x & 31;
    int r = blockIdx.x * 8 + wid;          // b*T + t
    int b = r >> 7;
    const float* e = en + (size_t)r * S_;
    const float* m = mask + (size_t)b * S_;

    float x[16], mv[16];
    #pragma unroll
    for (int j = 0; j < 4; j++){
        int base = j * 128 + lane * 4;
        float4 ev = *(const float4*)(e + base);
        float4 mvv = *(const float4*)(m + base);
        mv[j*4+0]=mvv.x; mv[j*4+1]=mvv.y; mv[j*4+2]=mvv.z; mv[j*4+3]=mvv.w;
        x[j*4+0]=ev.x*mvv.x; x[j*4+1]=ev.y*mvv.y; x[j*4+2]=ev.z*mvv.z; x[j*4+3]=ev.w*mvv.w;
    }
    float mx = x[0];
    #pragma unroll
    for (int i = 1; i < 16; i++) mx = fmaxf(mx, x[i]);
    #pragma unroll
    for (int o = 16; o; o >>= 1) mx = fmaxf(mx, __shfl_xor_sync(0xffffffffu, mx, o));

    float s = 0.f;
    #pragma unroll
    for (int i = 0; i < 16; i++){
        x[i] = __expf(x[i] - mx) * mv[i];
        s += x[i];
    }
    #pragma unroll
    for (int o = 16; o; o >>= 1) s += __shfl_xor_sync(0xffffffffu, s, o);
    float inv = 1.0f / (s + 1e-6f);

    size_t base_o = (size_t)r * S_;
    #pragma unroll
    for (int j = 0; j < 4; j++){
        int base = j * 128 + lane * 4;
        float a0 = x[j*4+0]*inv, a1 = x[j*4+1]*inv, a2 = x[j*4+2]*inv, a3 = x[j*4+3]*inv;
        *(float4*)(attn + base_o + base) = make_float4(a0, a1, a2, a3);
        __nv_bfloat16 h[4], l[4];
        float vv[4] = {a0, a1, a2, a3};
        #pragma unroll
        for (int q = 0; q < 4; q++){
            h[q] = __float2bfloat16_rn(vv[q]);
            l[q] = __float2bfloat16_rn(vv[q] - __bfloat162float(h[q]));
        }
        *(ushort4*)(ah + base_o + base) = *(ushort4*)h;
        *(ushort4*)(al + base_o + base) = *(ushort4*)l;
    }
}

// ---------------------------------------------------------------------------
extern "C" void kernel_launch(void* const* d_in, const int* in_sizes, int n_in,
                              void* d_out, int out_size)
{
    const float* hidden = (const float*)d_in[0];
    const float* enc    = (const float*)d_in[1];
    const float* mask   = (const float*)d_in[2];
    const float* W_attn = (const float*)d_in[3];
    const float* b_attn = (const float*)d_in[4];
    const float* W_v    = (const float*)d_in[5];
    const float* b_v    = (const float*)d_in[6];
    const float* W_out  = (const float*)d_in[7];

    float* out     = (float*)d_out;
    float* h_tilde = out;
    float* wc      = out + (size_t)B_*T_*D_;
    float* attn    = wc  + (size_t)B_*T_*E_;

    float *hp, *ep, *en, *p0, *p1, *p2, *p3;
    cudaGetSymbolAddress((void**)&hp, g_hp);
    cudaGetSymbolAddress((void**)&ep, g_ep);
    cudaGetSymbolAddress((void**)&en, g_en);
    cudaGetSymbolAddress((void**)&p0, g_p0);
    cudaGetSymbolAddress((void**)&p1, g_p1);
    cudaGetSymbolAddress((void**)&p2, g_p2);
    cudaGetSymbolAddress((void**)&p3, g_p3);
    __nv_bfloat16 *hid_h,*hid_l,*enc_h,*enc_l,*encT_h,*encT_l,*Wa_h,*Wa_l,*Wo_h,*Wo_l,*at_h,*at_l,*wc_h,*wc_l;
    cudaGetSymbolAddress((void**)&hid_h, g_hid_h);  cudaGetSymbolAddress((void**)&hid_l, g_hid_l);
    cudaGetSymbolAddress((void**)&enc_h, g_enc_h);  cudaGetSymbolAddress((void**)&enc_l, g_enc_l);
    cudaGetSymbolAddress((void**)&encT_h, g_encT_h);cudaGetSymbolAddress((void**)&encT_l, g_encT_l);
    cudaGetSymbolAddress((void**)&Wa_h, g_Wa_h);    cudaGetSymbolAddress((void**)&Wa_l, g_Wa_l);
    cudaGetSymbolAddress((void**)&Wo_h, g_Wo_h);    cudaGetSymbolAddress((void**)&Wo_l, g_Wo_l);
    cudaGetSymbolAddress((void**)&at_h, g_attn_h);  cudaGetSymbolAddress((void**)&at_l, g_attn_l);
    cudaGetSymbolAddress((void**)&wc_h, g_wc_h);    cudaGetSymbolAddress((void**)&wc_l, g_wc_l);

    cudaFuncSetAttribute(gemm64_dual_kernel, cudaFuncAttributeMaxDynamicSharedMemorySize, GS64);
    cudaFuncSetAttribute(gemm64_ks4_kernel,  cudaFuncAttributeMaxDynamicSharedMemorySize, GS64);

    // fused prep: hidden/W_attn/W_out splits + enc split/transpose-split
    int nb0 = (B_*T_*D_)/1024, nb1 = (D_*(E_+D_))/1024, nb2 = (D_*(E_+D_))/1024;
    int ntr = (S_/32)*(E_/32)*B_;   // 2048 transpose blocks
    prep_all_kernel<<<nb0+nb1+nb2+ntr, 256>>>(
        hidden, hid_h, hid_l, nb0,
        W_attn, Wa_h,  Wa_l,  nb1,
        W_out,  Wo_h,  Wo_l,  nb2,
        enc, enc_h, enc_l, encT_h, encT_l);

    // fused hp (job0: M=1024, 16 mtiles) + ep (job1: M=4096, 64 mtiles); N=512, K=512
    gemm64_dual_kernel<<<128 + 512, 128, GS64>>>(
        hid_h, hid_l, D_, Wa_h, Wa_l, E_+D_, hp, D_, b_attn, 16, 128,
        enc_h, enc_l, E_, Wa_h + D_, Wa_l + D_, E_+D_, ep, D_, 64,
        16);

    // energies: 16t x 64s tiles, BK=32 (proven config)
    energies_kernel<<<dim3(S_/64, T_/16, B_), 256>>>(hp, ep, W_v, b_v, mask, en);
    // softmax -> attn (+ bf16 split): warp-per-row, 128 blocks
    softmax_kernel<<<dim3(B_*T_/8), 256>>>(en, mask, attn, at_h, at_l);

    // wc = attn @ encT^T (batched, M=128, N=512, K=512), split-K x4 (kstep=128)
    gemm64_ks4_kernel<<<dim3(4*2, E_/64, B_), 128, GS64>>>(
        at_h, at_l, at_h, at_l, 4, 128, S_, (long long)T_*S_,
        encT_h, encT_l, S_, (long long)E_*S_,
        p0, p1, p2, p3, E_, (long long)T_*E_, 4, 2);
    combine_wc_kernel<<<(B_*T_*E_)/1024, 256>>>(p0, p1, p2, p3, wc, wc_h, wc_l);

    // h_tilde = tanh(concat(wc, hidden) @ W_out^T), split-K x4:
    // ks 0,1 -> wc slices (kstep=256); ks 2,3 -> hidden slices.  B offset = ks*256.
    gemm64_ks4_kernel<<<dim3(4*16, D_/64, 1), 128, GS64>>>(
        wc_h, wc_l, hid_h, hid_l, 2, 256, E_, 0,
        Wo_h, Wo_l, E_+D_, 0,
        p0, p1, p2, p3, D_, 0, 8, 16);
    combine_ht_kernel<<<(B_*T_*D_)/1024, 256>>>(p0, p1, p2, p3, h_tilde);
}